// round 12
// baseline (speedup 1.0000x reference)
#include <cuda_runtime.h>
#include <cuda_fp16.h>
#include <math.h>
#include <stdint.h>

// Problem constants (fixed by setup_inputs)
#define BB    4
#define NTOK  6400
#define DM    256
#define HH    8
#define HD    32
#define PP    9
#define HIMG  40
#define WIMG  160
#define MROWS (BB * NTOK)   // 25600
#define KK    256

// ---------------- scratch (device globals; no allocation allowed) ----------
__device__ float   g_q  [(size_t)MROWS * DM];
__device__ float   g_off[(size_t)MROWS * HH * PP * 2];       // tanh(..)*4 offsets
__device__ __align__(16) __half2  g_kvh[(size_t)MROWS * DM]; // packed (k,v) fp16 per ch

__device__ __align__(16) uint16_t g_xh[(size_t)MROWS * KK];  // x fp16
__device__ __align__(16) uint16_t g_ah[(size_t)MROWS * DM];  // attention out fp16

__device__ __align__(16) uint16_t g_wq [256 * KK];
__device__ __align__(16) uint16_t g_wo [144 * KK];
__device__ __align__(16) uint16_t g_wkv[512 * KK];
__device__ __align__(16) uint16_t g_wu [256 * KK];

// ---------------- warp MMA helpers (base-ISA) ------------------------------
__device__ __forceinline__ uint32_t smem_u32(const void* p) {
    uint32_t a;
    asm("{ .reg .u64 t; cvta.to.shared.u64 t, %1; cvt.u32.u64 %0, t; }" : "=r"(a) : "l"(p));
    return a;
}
__device__ __forceinline__ void ldsm_x4(uint32_t* r, uint32_t addr) {
    asm volatile("ldmatrix.sync.aligned.m8n8.x4.shared.b16 {%0,%1,%2,%3}, [%4];"
        : "=r"(r[0]), "=r"(r[1]), "=r"(r[2]), "=r"(r[3]) : "r"(addr));
}
__device__ __forceinline__ void mma16816_f16(float* c, const uint32_t* a, const uint32_t* b) {
    asm volatile("mma.sync.aligned.m16n8k16.row.col.f32.f16.f16.f32 "
        "{%0,%1,%2,%3}, {%4,%5,%6,%7}, {%8,%9}, {%0,%1,%2,%3};"
        : "+f"(c[0]), "+f"(c[1]), "+f"(c[2]), "+f"(c[3])
        : "r"(a[0]), "r"(a[1]), "r"(a[2]), "r"(a[3]), "r"(b[0]), "r"(b[1]));
}
#define CP_ASYNC16(dst, src) asm volatile("cp.async.cg.shared.global [%0], [%1], 16;" :: "r"(dst), "l"(src))
#define CP_COMMIT()          asm volatile("cp.async.commit_group;" ::: "memory")
#define CP_WAIT2()           asm volatile("cp.async.wait_group 2;" ::: "memory")
#define CP_WAIT1()           asm volatile("cp.async.wait_group 1;" ::: "memory")
#define CP_WAIT0()           asm volatile("cp.async.wait_group 0;" ::: "memory")

// ---------------- packed f32x2 helpers (bit-exact vs scalar fp32) ----------
__device__ __forceinline__ unsigned long long cvt_h2_f32x2(uint32_t h2) {
    unsigned long long r;
    asm("{\n\t.reg .b16 lo, hi;\n\t.reg .f32 flo, fhi;\n\t"
        "mov.b32 {lo, hi}, %1;\n\t"
        "cvt.f32.f16 flo, lo;\n\t"
        "cvt.f32.f16 fhi, hi;\n\t"
        "mov.b64 %0, {flo, fhi};\n\t}"
        : "=l"(r) : "r"(h2));
    return r;
}
__device__ __forceinline__ unsigned long long pack2(float a, float b) {
    unsigned long long r;
    asm("mov.b64 %0, {%1, %2};" : "=l"(r) : "f"(a), "f"(b));
    return r;
}
__device__ __forceinline__ void unpack2(unsigned long long v, float& a, float& b) {
    asm("mov.b64 {%0, %1}, %2;" : "=f"(a), "=f"(b) : "l"(v));
}
__device__ __forceinline__ void fma2(unsigned long long& acc, unsigned long long w,
                                     unsigned long long v) {
    asm("fma.rn.f32x2 %0, %1, %2, %0;" : "+l"(acc) : "l"(w), "l"(v));
}

// SMEM: 3-stage buffered A [128][72], B [128][72] fp16
#define LDS  72
#define B_A 0
#define B_B (128 * LDS)
#define BUF_ELEMS (2 * 128 * LDS)            // 18432 elems = 36864 B / stage
#define SM_BYTES  (3 * BUF_ELEMS * 2)        // 110592 B -> 2 CTAs/SM (221KB < 228KB)

// ---------------------------------------------------------------------------
__device__ __forceinline__ void load_chunk_async(
    uint16_t* smb, const uint16_t* __restrict__ A, const uint16_t* __restrict__ W,
    int Nc, int m0, int n0, int k0, int tid)
{
    // A: 1024 16B-chunks, 4 per thread
#pragma unroll
    for (int i = 0; i < 4; i++) {
        int idx = tid + i * 256;
        int row = idx >> 3;
        int kc  = (idx & 7) * 8;
        const uint16_t* src = A + (size_t)(m0 + row) * KK + k0 + kc;
        CP_ASYNC16(smem_u32(smb + B_A + row * LDS + kc), src);
    }
    // B: 1024 chunks, 4 per thread (row clamped; junk cols skipped in epilogue)
#pragma unroll
    for (int i = 0; i < 4; i++) {
        int idx = tid + i * 256;
        int row = idx >> 3;
        int kc  = (idx & 7) * 8;
        int gr  = n0 + row; if (gr > Nc - 1) gr = Nc - 1;
        const uint16_t* src = W + (size_t)gr * KK + k0 + kc;
        CP_ASYNC16(smem_u32(smb + B_B + row * LDS + kc), src);
    }
}

// C[m0:m0+128, n0:n0+128] = A @ W^T + bias (fp16 MMA, fp32 accum)
// mode: 0 plain fp32, 1 tanh*4, 2 kv->fp16 interleave pack
__device__ __forceinline__ void gemm_tile_f16(
    const uint16_t* __restrict__ A, const uint16_t* __restrict__ W,
    const float* __restrict__ bias, float* __restrict__ C,
    int Nc, int ldC, int m0, int n0, int mode)
{
    extern __shared__ uint16_t sm[];
    const int tid = threadIdx.x;
    const int wid = tid >> 5, lane = tid & 31;
    const int wm = (wid & 3) * 32;          // 4 warps in M
    const int wn = (wid >> 2) * 64;         // 2 warps in N

    float acc[2][8][4];
#pragma unroll
    for (int mt = 0; mt < 2; mt++)
#pragma unroll
        for (int nt = 0; nt < 8; nt++)
#pragma unroll
            for (int i = 0; i < 4; i++) acc[mt][nt][i] = 0.f;

    const int a_r = lane & 15;
    const int a_c = (lane >> 4) * 8;
    const int bp_r = ((lane >> 4) & 1) * 8 + (lane & 7);
    const int bp_c = ((lane >> 3) & 1) * 8;

    load_chunk_async(sm,             A, W, Nc, m0, n0, 0,  tid);
    CP_COMMIT();
    load_chunk_async(sm + BUF_ELEMS, A, W, Nc, m0, n0, 64, tid);
    CP_COMMIT();

#pragma unroll 1
    for (int kc4 = 0; kc4 < 4; kc4++) {
        uint16_t* cur = sm + (kc4 % 3) * BUF_ELEMS;
        if (kc4 < 2) {
            load_chunk_async(sm + ((kc4 + 2) % 3) * BUF_ELEMS,
                             A, W, Nc, m0, n0, (kc4 + 2) * 64, tid);
            CP_COMMIT();
            CP_WAIT2();
        } else if (kc4 == 2) {
            CP_WAIT1();
        } else {
            CP_WAIT0();
        }
        __syncthreads();

#pragma unroll
        for (int ks = 0; ks < 4; ks++) {
            const int kb = ks * 16;
            uint32_t af[2][4];
#pragma unroll
            for (int mt = 0; mt < 2; mt++) {
                int row = wm + mt * 16 + a_r;
                ldsm_x4(af[mt], smem_u32(cur + B_A + row * LDS + kb + a_c));
            }
            uint32_t bf[16];
#pragma unroll
            for (int np = 0; np < 4; np++) {
                int row = wn + np * 16 + bp_r;
                ldsm_x4(bf + np * 4, smem_u32(cur + B_B + row * LDS + kb + bp_c));
            }
#pragma unroll
            for (int mt = 0; mt < 2; mt++)
#pragma unroll
                for (int nt = 0; nt < 8; nt++)
                    mma16816_f16(acc[mt][nt], af[mt], bf + nt * 2);
        }
        __syncthreads();
    }

    // ---- epilogue
    const int er = lane >> 2;
    const int ec = (lane & 3) * 2;
#pragma unroll
    for (int mt = 0; mt < 2; mt++) {
#pragma unroll
        for (int half = 0; half < 2; half++) {
            int gm = m0 + wm + mt * 16 + er + half * 8;
#pragma unroll
            for (int nt = 0; nt < 8; nt++) {
                int gn = n0 + wn + nt * 8 + ec;
                if (gn < Nc) {
                    float v0 = acc[mt][nt][half * 2 + 0] + bias[gn];
                    float v1 = acc[mt][nt][half * 2 + 1] + bias[gn + 1];
                    if (mode == 1) { v0 = tanhf(v0) * 4.f; v1 = tanhf(v1) * 4.f; }
                    if (mode == 2) {
                        // kv channel-interleave fp16: k ch c -> slot 2c, v ch c -> 2c+1
                        uint16_t* kvh = (uint16_t*)g_kvh + (size_t)gm * 512;
                        int c0 = (gn < 256) ? gn * 2       : (gn - 256) * 2 + 1;
                        int c1 = (gn < 255) ? (gn + 1) * 2 : (gn + 1 - 256) * 2 + 1;
                        kvh[c0] = __half_as_ushort(__float2half_rn(v0));
                        kvh[c1] = __half_as_ushort(__float2half_rn(v1));
                    } else {
                        float* crow = C + (size_t)gm * ldC;
                        crow[gn]     = v0;
                        crow[gn + 1] = v1;
                    }
                }
            }
        }
    }
}

// in_gemm: blockIdx.x: 0-1 q | 2-3 off(tanh) | 4-7 kv(fp16 pack)
__global__ __launch_bounds__(256, 2)
void in_gemm_mma(const float* __restrict__ bq, const float* __restrict__ bo,
                 const float* __restrict__ bkv)
{
    const int t = blockIdx.x;
    const int m0 = blockIdx.y * 128;
    if (t < 2)
        gemm_tile_f16(g_xh, g_wq, bq, g_q, 256, 256, m0, t * 128, 0);
    else if (t < 4)
        gemm_tile_f16(g_xh, g_wo, bo, g_off, 144, 144, m0, (t - 2) * 128, 1);
    else
        gemm_tile_f16(g_xh, g_wkv, bkv, nullptr, 512, 512, m0, (t - 4) * 128, 2);
}

__global__ __launch_bounds__(256, 2)
void out_gemm_mma(const float* __restrict__ bout, float* __restrict__ C)
{
    gemm_tile_f16(g_ah, g_wu, bout, C, 256, 256, blockIdx.y * 128, blockIdx.x * 128, 0);
}

// ---------------------------------------------------------------------------
// fp32 -> fp16 converts (x and all weights, single launch)
// ---------------------------------------------------------------------------
#define CONVX_BLOCKS ((MROWS * KK / 4) / 256)     // 6400
#define CONVW_BLOCKS (299008 / 256)               // 1168
__global__ __launch_bounds__(256)
void conv_all_kernel(const float* __restrict__ x,
                     const float* __restrict__ Wq, const float* __restrict__ Wo,
                     const float* __restrict__ Wkv, const float* __restrict__ Wu)
{
    int bid = blockIdx.x;
    if (bid < CONVX_BLOCKS) {
        int i4 = bid * 256 + threadIdx.x;
        float4 v = ((const float4*)x)[i4];
        uint16_t h[4];
        h[0] = __half_as_ushort(__float2half_rn(v.x));
        h[1] = __half_as_ushort(__float2half_rn(v.y));
        h[2] = __half_as_ushort(__float2half_rn(v.z));
        h[3] = __half_as_ushort(__float2half_rn(v.w));
        ((uint64_t*)g_xh)[i4] = *(const uint64_t*)h;
    } else {
        int i = (bid - CONVX_BLOCKS) * 256 + threadIdx.x;
        const float* src; uint16_t* dst; int off;
        if (i < 65536)        { src = Wq;  dst = g_wq;  off = i; }
        else if (i < 102400)  { src = Wo;  dst = g_wo;  off = i - 65536; }
        else if (i < 233472)  { src = Wkv; dst = g_wkv; off = i - 102400; }
        else                  { src = Wu;  dst = g_wu;  off = i - 233472; }
        dst[off] = __half_as_ushort(__float2half_rn(src[off]));
    }
}

// ---------------------------------------------------------------------------
// Deformable attention: 4 heads/warp, streaming softmax, packed f32x2 accum.
// acc[i] = (ka_i, va_i) packed; one fma.rn.f32x2 per channel-corner.
// ---------------------------------------------------------------------------
__global__ __launch_bounds__(256, 6)
void deform_attn_kernel()
{
    const int wid = threadIdx.x >> 5;
    const int lane = threadIdx.x & 31;
    const int token = blockIdx.x * 4 + (wid >> 1);
    const int b = token / NTOK;
    const int n = token - b * NTOK;
    const int h = (wid & 1) * 4 + (lane >> 3);
    const int cg = lane & 7;

    const float xbase = (float)(n % WIMG);
    const float ybase = (float)(n / WIMG);

    const int chan = h * HD + cg * 4;
    const float4 qv = *(const float4*)(g_q + (size_t)token * DM + chan);
    const float2* offp = (const float2*)(g_off + (size_t)token * (HH * PP * 2) + h * PP * 2);
    const __half2* kvb = g_kvh + (size_t)b * NTOK * 256 + chan;

    const float scale = 0.17677669529663687f;   // 1/sqrt(32)
    float sum = 0.f;
    unsigned long long oacc[4] = {0, 0, 0, 0};  // (junk_k, o_v) packed

#pragma unroll
    for (int p = 0; p < PP; p++) {
        float2 o = __ldg(&offp[p]);
        float sx = xbase + o.x;
        float sy = ybase + o.y;
        float x0f = floorf(sx), y0f = floorf(sy);
        int x0 = (int)x0f, y0 = (int)y0f;
        float wx1 = sx - x0f, wx0 = 1.f - wx1;
        float wy1 = sy - y0f, wy0 = 1.f - wy1;

        unsigned long long acc[4] = {0, 0, 0, 0};   // (ka_i, va_i)

        if ((unsigned)x0 < (unsigned)(WIMG - 1) && (unsigned)y0 < (unsigned)(HIMG - 1)) {
            const __half2* p00 = kvb + (size_t)(y0 * WIMG + x0) * 256;
            const float w[4] = {wx0 * wy0, wx1 * wy0, wx0 * wy1, wx1 * wy1};
            const size_t co[4] = {0, 256, (size_t)WIMG * 256, (size_t)(WIMG + 1) * 256};
#pragma unroll
            for (int c = 0; c < 4; c++) {
                uint4 raw = *(const uint4*)(p00 + co[c]);
                unsigned long long w2 = pack2(w[c], w[c]);
                const uint32_t* hp = (const uint32_t*)&raw;
#pragma unroll
                for (int i = 0; i < 4; i++)
                    fma2(acc[i], w2, cvt_h2_f32x2(hp[i]));
            }
        } else {
#pragma unroll
            for (int cy = 0; cy < 2; cy++) {
                int yy = y0 + cy;
                if ((unsigned)yy >= (unsigned)HIMG) continue;
                float wy = cy ? wy1 : wy0;
#pragma unroll
                for (int cx = 0; cx < 2; cx++) {
                    int xx = x0 + cx;
                    if ((unsigned)xx >= (unsigned)WIMG) continue;
                    float wgt = (cx ? wx1 : wx0) * wy;
                    uint4 raw = *(const uint4*)(kvb + (size_t)(yy * WIMG + xx) * 256);
                    unsigned long long w2 = pack2(wgt, wgt);
                    const uint32_t* hp = (const uint32_t*)&raw;
#pragma unroll
                    for (int i = 0; i < 4; i++)
                        fma2(acc[i], w2, cvt_h2_f32x2(hp[i]));
                }
            }
        }

        float ka0, va0, ka1, va1, ka2, va2, ka3, va3;
        unpack2(acc[0], ka0, va0);
        unpack2(acc[1], ka1, va1);
        unpack2(acc[2], ka2, va2);
        unpack2(acc[3], ka3, va3);
        (void)va0; (void)va1; (void)va2; (void)va3;

        float d = qv.x * ka0;
        d = fmaf(qv.y, ka1, d);
        d = fmaf(qv.z, ka2, d);
        d = fmaf(qv.w, ka3, d);
        d += __shfl_xor_sync(0xffffffffu, d, 1);
        d += __shfl_xor_sync(0xffffffffu, d, 2);
        d += __shfl_xor_sync(0xffffffffu, d, 4);

        float e = __expf(d * scale);
        sum += e;
        unsigned long long e2 = pack2(e, e);
        fma2(oacc[0], e2, acc[0]);
        fma2(oacc[1], e2, acc[1]);
        fma2(oacc[2], e2, acc[2]);
        fma2(oacc[3], e2, acc[3]);
    }

    float inv = 1.f / sum;
    float j0, o0, j1, o1, j2, o2, j3, o3;
    unpack2(oacc[0], j0, o0);
    unpack2(oacc[1], j1, o1);
    unpack2(oacc[2], j2, o2);
    unpack2(oacc[3], j3, o3);
    (void)j0; (void)j1; (void)j2; (void)j3;

    uint16_t hv[4];
    hv[0] = __half_as_ushort(__float2half_rn(o0 * inv));
    hv[1] = __half_as_ushort(__float2half_rn(o1 * inv));
    hv[2] = __half_as_ushort(__float2half_rn(o2 * inv));
    hv[3] = __half_as_ushort(__float2half_rn(o3 * inv));
    size_t oi = (size_t)token * DM + chan;
    *(uint64_t*)(g_ah + oi) = *(const uint64_t*)hv;
}

// ---------------------------------------------------------------------------
extern "C" void kernel_launch(void* const* d_in, const int* in_sizes, int n_in,
                              void* d_out, int out_size) {
    const float* x    = (const float*)d_in[0];
    const float* Wq   = (const float*)d_in[1];
    const float* bq   = (const float*)d_in[2];
    const float* Woff = (const float*)d_in[3];
    const float* boff = (const float*)d_in[4];
    const float* Wkv  = (const float*)d_in[5];
    const float* bkv  = (const float*)d_in[6];
    const float* Wout = (const float*)d_in[7];
    const float* bout = (const float*)d_in[8];
    float* out = (float*)d_out;

    static bool attr_done = false;
    if (!attr_done) {
        cudaFuncSetAttribute(in_gemm_mma,  cudaFuncAttributeMaxDynamicSharedMemorySize, SM_BYTES);
        cudaFuncSetAttribute(out_gemm_mma, cudaFuncAttributeMaxDynamicSharedMemorySize, SM_BYTES);
        attr_done = true;
    }

    conv_all_kernel<<<CONVX_BLOCKS + CONVW_BLOCKS, 256>>>(x, Wq, Woff, Wkv, Wout);

    in_gemm_mma<<<dim3(8, MROWS / 128), 256, SM_BYTES>>>(bq, boff, bkv);

    deform_attn_kernel<<<MROWS / 4, 256>>>();

    out_gemm_mma<<<dim3(2, MROWS / 128), 256, SM_BYTES>>>(bout, out);
}

// round 13
// speedup vs baseline: 1.0550x; 1.0550x over previous
#include <cuda_runtime.h>
#include <cuda_fp16.h>
#include <math.h>
#include <stdint.h>

// Problem constants (fixed by setup_inputs)
#define BB    4
#define NTOK  6400
#define DM    256
#define HH    8
#define HD    32
#define PP    9
#define HIMG  40
#define WIMG  160
#define MROWS (BB * NTOK)   // 25600
#define KK    256

// ---------------- scratch (device globals; no allocation allowed) ----------
__device__ float   g_q  [(size_t)MROWS * DM];
__device__ float   g_off[(size_t)MROWS * HH * PP * 2];       // tanh(..)*4 offsets
__device__ __align__(16) __half2  g_kvh[(size_t)MROWS * DM]; // packed (k,v) fp16 per ch

__device__ __align__(16) uint16_t g_xh[(size_t)MROWS * KK];  // x fp16
__device__ __align__(16) uint16_t g_ah[(size_t)MROWS * DM];  // attention out fp16

__device__ __align__(16) uint16_t g_wq [256 * KK];
__device__ __align__(16) uint16_t g_wo [144 * KK];
__device__ __align__(16) uint16_t g_wkv[512 * KK];
__device__ __align__(16) uint16_t g_wu [256 * KK];

// ---------------- warp MMA helpers (base-ISA) ------------------------------
__device__ __forceinline__ uint32_t smem_u32(const void* p) {
    uint32_t a;
    asm("{ .reg .u64 t; cvta.to.shared.u64 t, %1; cvt.u32.u64 %0, t; }" : "=r"(a) : "l"(p));
    return a;
}
__device__ __forceinline__ void ldsm_x4(uint32_t* r, uint32_t addr) {
    asm volatile("ldmatrix.sync.aligned.m8n8.x4.shared.b16 {%0,%1,%2,%3}, [%4];"
        : "=r"(r[0]), "=r"(r[1]), "=r"(r[2]), "=r"(r[3]) : "r"(addr));
}
__device__ __forceinline__ void mma16816_f16(float* c, const uint32_t* a, const uint32_t* b) {
    asm volatile("mma.sync.aligned.m16n8k16.row.col.f32.f16.f16.f32 "
        "{%0,%1,%2,%3}, {%4,%5,%6,%7}, {%8,%9}, {%0,%1,%2,%3};"
        : "+f"(c[0]), "+f"(c[1]), "+f"(c[2]), "+f"(c[3])
        : "r"(a[0]), "r"(a[1]), "r"(a[2]), "r"(a[3]), "r"(b[0]), "r"(b[1]));
}
#define CP_ASYNC16(dst, src) asm volatile("cp.async.cg.shared.global [%0], [%1], 16;" :: "r"(dst), "l"(src))
#define CP_COMMIT()          asm volatile("cp.async.commit_group;" ::: "memory")
#define CP_WAIT1()           asm volatile("cp.async.wait_group 1;" ::: "memory")
#define CP_WAIT0()           asm volatile("cp.async.wait_group 0;" ::: "memory")

// ---------------- packed f32x2 helpers (bit-exact vs scalar fp32) ----------
__device__ __forceinline__ unsigned long long cvt_h2_f32x2(uint32_t h2) {
    unsigned long long r;
    asm("{\n\t.reg .b16 lo, hi;\n\t.reg .f32 flo, fhi;\n\t"
        "mov.b32 {lo, hi}, %1;\n\t"
        "cvt.f32.f16 flo, lo;\n\t"
        "cvt.f32.f16 fhi, hi;\n\t"
        "mov.b64 %0, {flo, fhi};\n\t}"
        : "=l"(r) : "r"(h2));
    return r;
}
__device__ __forceinline__ unsigned long long pack2(float a, float b) {
    unsigned long long r;
    asm("mov.b64 %0, {%1, %2};" : "=l"(r) : "f"(a), "f"(b));
    return r;
}
__device__ __forceinline__ void unpack2(unsigned long long v, float& a, float& b) {
    asm("mov.b64 {%0, %1}, %2;" : "=f"(a), "=f"(b) : "l"(v));
}
__device__ __forceinline__ void fma2(unsigned long long& acc, unsigned long long w,
                                     unsigned long long v) {
    asm("fma.rn.f32x2 %0, %1, %2, %0;" : "+l"(acc) : "l"(w), "l"(v));
}

// SMEM: 2-stage buffered A [128][72], B [64][72] fp16  (55.3 KB -> 4 CTAs/SM)
#define LDS  72
#define B_A 0
#define B_B (128 * LDS)
#define BUF_ELEMS (128 * LDS + 64 * LDS)     // 13824 elems = 27648 B / stage
#define SM_BYTES  (2 * BUF_ELEMS * 2)        // 55296 B

// ---------------------------------------------------------------------------
__device__ __forceinline__ void load_chunk_async(
    uint16_t* smb, const uint16_t* __restrict__ A, const uint16_t* __restrict__ W,
    int Nc, int m0, int n0, int k0, int tid)
{
    // A: 1024 16B-chunks, 4 per thread
#pragma unroll
    for (int i = 0; i < 4; i++) {
        int idx = tid + i * 256;
        int row = idx >> 3;
        int kc  = (idx & 7) * 8;
        const uint16_t* src = A + (size_t)(m0 + row) * KK + k0 + kc;
        CP_ASYNC16(smem_u32(smb + B_A + row * LDS + kc), src);
    }
    // B: 512 chunks, 2 per thread (row clamped; junk cols skipped in epilogue)
#pragma unroll
    for (int i = 0; i < 2; i++) {
        int idx = tid + i * 256;
        int row = idx >> 3;
        int kc  = (idx & 7) * 8;
        int gr  = n0 + row; if (gr > Nc - 1) gr = Nc - 1;
        const uint16_t* src = W + (size_t)gr * KK + k0 + kc;
        CP_ASYNC16(smem_u32(smb + B_B + row * LDS + kc), src);
    }
}

// C[m0:m0+128, n0:n0+64] = A @ W^T + bias (fp16 MMA, fp32 accum)
// mode: 0 plain fp32, 1 tanh*4, 2 kv->fp16 interleave pack
__device__ __forceinline__ void gemm_tile_f16(
    const uint16_t* __restrict__ A, const uint16_t* __restrict__ W,
    const float* __restrict__ bias, float* __restrict__ C,
    int Nc, int ldC, int m0, int n0, int mode)
{
    extern __shared__ uint16_t sm[];
    const int tid = threadIdx.x;
    const int wid = tid >> 5, lane = tid & 31;
    const int wm = (wid & 3) * 32;          // 4 warps in M
    const int wn = (wid >> 2) * 32;         // 2 warps in N

    float acc[2][4][4];
#pragma unroll
    for (int mt = 0; mt < 2; mt++)
#pragma unroll
        for (int nt = 0; nt < 4; nt++)
#pragma unroll
            for (int i = 0; i < 4; i++) acc[mt][nt][i] = 0.f;

    const int a_r = lane & 15;
    const int a_c = (lane >> 4) * 8;
    const int bp_r = ((lane >> 4) & 1) * 8 + (lane & 7);   // row within 16-row pair
    const int bp_c = ((lane >> 3) & 1) * 8;

    load_chunk_async(sm, A, W, Nc, m0, n0, 0, tid);
    CP_COMMIT();

#pragma unroll 1
    for (int kc4 = 0; kc4 < 4; kc4++) {
        uint16_t* cur = sm + (kc4 & 1) * BUF_ELEMS;
        if (kc4 < 3) {
            load_chunk_async(sm + ((kc4 + 1) & 1) * BUF_ELEMS,
                             A, W, Nc, m0, n0, (kc4 + 1) * 64, tid);
            CP_COMMIT();
            CP_WAIT1();
        } else {
            CP_WAIT0();
        }
        __syncthreads();

#pragma unroll
        for (int ks = 0; ks < 4; ks++) {
            const int kb = ks * 16;
            uint32_t af[2][4];
#pragma unroll
            for (int mt = 0; mt < 2; mt++) {
                int row = wm + mt * 16 + a_r;
                ldsm_x4(af[mt], smem_u32(cur + B_A + row * LDS + kb + a_c));
            }
            uint32_t bf[8];
#pragma unroll
            for (int np = 0; np < 2; np++) {      // pairs of 8-col n-tiles
                int row = wn + np * 16 + bp_r;
                ldsm_x4(bf + np * 4, smem_u32(cur + B_B + row * LDS + kb + bp_c));
            }
#pragma unroll
            for (int mt = 0; mt < 2; mt++)
#pragma unroll
                for (int nt = 0; nt < 4; nt++)
                    mma16816_f16(acc[mt][nt], af[mt], bf + nt * 2);
        }
        __syncthreads();
    }

    // ---- epilogue
    const int er = lane >> 2;
    const int ec = (lane & 3) * 2;
#pragma unroll
    for (int mt = 0; mt < 2; mt++) {
#pragma unroll
        for (int half = 0; half < 2; half++) {
            int gm = m0 + wm + mt * 16 + er + half * 8;
#pragma unroll
            for (int nt = 0; nt < 4; nt++) {
                int gn = n0 + wn + nt * 8 + ec;
                if (gn < Nc) {
                    float v0 = acc[mt][nt][half * 2 + 0] + bias[gn];
                    float v1 = acc[mt][nt][half * 2 + 1] + bias[gn + 1];
                    if (mode == 1) { v0 = tanhf(v0) * 4.f; v1 = tanhf(v1) * 4.f; }
                    if (mode == 2) {
                        // kv channel-interleave fp16: k ch c -> slot 2c, v ch c -> 2c+1
                        uint16_t* kvh = (uint16_t*)g_kvh + (size_t)gm * 512;
                        int c0 = (gn < 256) ? gn * 2       : (gn - 256) * 2 + 1;
                        int c1 = (gn < 255) ? (gn + 1) * 2 : (gn + 1 - 256) * 2 + 1;
                        kvh[c0] = __half_as_ushort(__float2half_rn(v0));
                        kvh[c1] = __half_as_ushort(__float2half_rn(v1));
                    } else {
                        float* crow = C + (size_t)gm * ldC;
                        crow[gn]     = v0;
                        crow[gn + 1] = v1;
                    }
                }
            }
        }
    }
}

// in_gemm: blockIdx.x: 0-3 q | 4-6 off(tanh) | 7-14 kv(fp16 pack)
__global__ __launch_bounds__(256, 4)
void in_gemm_mma(const float* __restrict__ bq, const float* __restrict__ bo,
                 const float* __restrict__ bkv)
{
    const int t = blockIdx.x;
    const int m0 = blockIdx.y * 128;
    if (t < 4)
        gemm_tile_f16(g_xh, g_wq, bq, g_q, 256, 256, m0, t * 64, 0);
    else if (t < 7)
        gemm_tile_f16(g_xh, g_wo, bo, g_off, 144, 144, m0, (t - 4) * 64, 1);
    else
        gemm_tile_f16(g_xh, g_wkv, bkv, nullptr, 512, 512, m0, (t - 7) * 64, 2);
}

__global__ __launch_bounds__(256, 4)
void out_gemm_mma(const float* __restrict__ bout, float* __restrict__ C)
{
    gemm_tile_f16(g_ah, g_wu, bout, C, 256, 256, blockIdx.y * 128, blockIdx.x * 64, 0);
}

// ---------------------------------------------------------------------------
// fp32 -> fp16 converts (x and all weights, single launch)
// ---------------------------------------------------------------------------
#define CONVX_BLOCKS ((MROWS * KK / 4) / 256)     // 6400
#define CONVW_BLOCKS (299008 / 256)               // 1168
__global__ __launch_bounds__(256)
void conv_all_kernel(const float* __restrict__ x,
                     const float* __restrict__ Wq, const float* __restrict__ Wo,
                     const float* __restrict__ Wkv, const float* __restrict__ Wu)
{
    int bid = blockIdx.x;
    if (bid < CONVX_BLOCKS) {
        int i4 = bid * 256 + threadIdx.x;
        float4 v = ((const float4*)x)[i4];
        uint16_t h[4];
        h[0] = __half_as_ushort(__float2half_rn(v.x));
        h[1] = __half_as_ushort(__float2half_rn(v.y));
        h[2] = __half_as_ushort(__float2half_rn(v.z));
        h[3] = __half_as_ushort(__float2half_rn(v.w));
        ((uint64_t*)g_xh)[i4] = *(const uint64_t*)h;
    } else {
        int i = (bid - CONVX_BLOCKS) * 256 + threadIdx.x;
        const float* src; uint16_t* dst; int off;
        if (i < 65536)        { src = Wq;  dst = g_wq;  off = i; }
        else if (i < 102400)  { src = Wo;  dst = g_wo;  off = i - 65536; }
        else if (i < 233472)  { src = Wkv; dst = g_wkv; off = i - 102400; }
        else                  { src = Wu;  dst = g_wu;  off = i - 233472; }
        dst[off] = __half_as_ushort(__float2half_rn(src[off]));
    }
}

// ---------------------------------------------------------------------------
// Deformable attention: 4 heads/warp, streaming softmax, packed f32x2 accum.
// ---------------------------------------------------------------------------
__global__ __launch_bounds__(256, 6)
void deform_attn_kernel()
{
    const int wid = threadIdx.x >> 5;
    const int lane = threadIdx.x & 31;
    const int token = blockIdx.x * 4 + (wid >> 1);
    const int b = token / NTOK;
    const int n = token - b * NTOK;
    const int h = (wid & 1) * 4 + (lane >> 3);
    const int cg = lane & 7;

    const float xbase = (float)(n % WIMG);
    const float ybase = (float)(n / WIMG);

    const int chan = h * HD + cg * 4;
    const float4 qv = *(const float4*)(g_q + (size_t)token * DM + chan);
    const float2* offp = (const float2*)(g_off + (size_t)token * (HH * PP * 2) + h * PP * 2);
    const __half2* kvb = g_kvh + (size_t)b * NTOK * 256 + chan;

    const float scale = 0.17677669529663687f;   // 1/sqrt(32)
    float sum = 0.f;
    unsigned long long oacc[4] = {0, 0, 0, 0};  // (junk_k, o_v) packed

#pragma unroll
    for (int p = 0; p < PP; p++) {
        float2 o = __ldg(&offp[p]);
        float sx = xbase + o.x;
        float sy = ybase + o.y;
        float x0f = floorf(sx), y0f = floorf(sy);
        int x0 = (int)x0f, y0 = (int)y0f;
        float wx1 = sx - x0f, wx0 = 1.f - wx1;
        float wy1 = sy - y0f, wy0 = 1.f - wy1;

        unsigned long long acc[4] = {0, 0, 0, 0};   // (ka_i, va_i)

        if ((unsigned)x0 < (unsigned)(WIMG - 1) && (unsigned)y0 < (unsigned)(HIMG - 1)) {
            const __half2* p00 = kvb + (size_t)(y0 * WIMG + x0) * 256;
            const float w[4] = {wx0 * wy0, wx1 * wy0, wx0 * wy1, wx1 * wy1};
            const size_t co[4] = {0, 256, (size_t)WIMG * 256, (size_t)(WIMG + 1) * 256};
#pragma unroll
            for (int c = 0; c < 4; c++) {
                uint4 raw = *(const uint4*)(p00 + co[c]);
                unsigned long long w2 = pack2(w[c], w[c]);
                const uint32_t* hp = (const uint32_t*)&raw;
#pragma unroll
                for (int i = 0; i < 4; i++)
                    fma2(acc[i], w2, cvt_h2_f32x2(hp[i]));
            }
        } else {
#pragma unroll
            for (int cy = 0; cy < 2; cy++) {
                int yy = y0 + cy;
                if ((unsigned)yy >= (unsigned)HIMG) continue;
                float wy = cy ? wy1 : wy0;
#pragma unroll
                for (int cx = 0; cx < 2; cx++) {
                    int xx = x0 + cx;
                    if ((unsigned)xx >= (unsigned)WIMG) continue;
                    float wgt = (cx ? wx1 : wx0) * wy;
                    uint4 raw = *(const uint4*)(kvb + (size_t)(yy * WIMG + xx) * 256);
                    unsigned long long w2 = pack2(wgt, wgt);
                    const uint32_t* hp = (const uint32_t*)&raw;
#pragma unroll
                    for (int i = 0; i < 4; i++)
                        fma2(acc[i], w2, cvt_h2_f32x2(hp[i]));
                }
            }
        }

        float ka0, va0, ka1, va1, ka2, va2, ka3, va3;
        unpack2(acc[0], ka0, va0);
        unpack2(acc[1], ka1, va1);
        unpack2(acc[2], ka2, va2);
        unpack2(acc[3], ka3, va3);
        (void)va0; (void)va1; (void)va2; (void)va3;

        float d = qv.x * ka0;
        d = fmaf(qv.y, ka1, d);
        d = fmaf(qv.z, ka2, d);
        d = fmaf(qv.w, ka3, d);
        d += __shfl_xor_sync(0xffffffffu, d, 1);
        d += __shfl_xor_sync(0xffffffffu, d, 2);
        d += __shfl_xor_sync(0xffffffffu, d, 4);

        float e = __expf(d * scale);
        sum += e;
        unsigned long long e2 = pack2(e, e);
        fma2(oacc[0], e2, acc[0]);
        fma2(oacc[1], e2, acc[1]);
        fma2(oacc[2], e2, acc[2]);
        fma2(oacc[3], e2, acc[3]);
    }

    float inv = 1.f / sum;
    float j0, o0, j1, o1, j2, o2, j3, o3;
    unpack2(oacc[0], j0, o0);
    unpack2(oacc[1], j1, o1);
    unpack2(oacc[2], j2, o2);
    unpack2(oacc[3], j3, o3);
    (void)j0; (void)j1; (void)j2; (void)j3;

    uint16_t hv[4];
    hv[0] = __half_as_ushort(__float2half_rn(o0 * inv));
    hv[1] = __half_as_ushort(__float2half_rn(o1 * inv));
    hv[2] = __half_as_ushort(__float2half_rn(o2 * inv));
    hv[3] = __half_as_ushort(__float2half_rn(o3 * inv));
    size_t oi = (size_t)token * DM + chan;
    *(uint64_t*)(g_ah + oi) = *(const uint64_t*)hv;
}

// ---------------------------------------------------------------------------
extern "C" void kernel_launch(void* const* d_in, const int* in_sizes, int n_in,
                              void* d_out, int out_size) {
    const float* x    = (const float*)d_in[0];
    const float* Wq   = (const float*)d_in[1];
    const float* bq   = (const float*)d_in[2];
    const float* Woff = (const float*)d_in[3];
    const float* boff = (const float*)d_in[4];
    const float* Wkv  = (const float*)d_in[5];
    const float* bkv  = (const float*)d_in[6];
    const float* Wout = (const float*)d_in[7];
    const float* bout = (const float*)d_in[8];
    float* out = (float*)d_out;

    static bool attr_done = false;
    if (!attr_done) {
        cudaFuncSetAttribute(in_gemm_mma,  cudaFuncAttributeMaxDynamicSharedMemorySize, SM_BYTES);
        cudaFuncSetAttribute(out_gemm_mma, cudaFuncAttributeMaxDynamicSharedMemorySize, SM_BYTES);
        attr_done = true;
    }

    conv_all_kernel<<<CONVX_BLOCKS + CONVW_BLOCKS, 256>>>(x, Wq, Woff, Wkv, Wout);

    in_gemm_mma<<<dim3(15, MROWS / 128), 256, SM_BYTES>>>(bq, boff, bkv);

    deform_attn_kernel<<<MROWS / 4, 256>>>();

    out_gemm_mma<<<dim3(4, MROWS / 128), 256, SM_BYTES>>>(bout, out);
}